// round 16
// baseline (speedup 1.0000x reference)
#include <cuda_runtime.h>
#include <cuda_fp16.h>
#include <math.h>
#include <stdint.h>

// ---------------- problem constants ----------------
#define BATCH    2
#define LQ       21760
#define LEN_IN   21760
#define DMODEL   256
#define NHEADS   8
#define HDIM     32
#define MROWS    (BATCH*LQ)       // 43520
#define NQP      384
#define KDIM     256
#define GPB      32
#define PGRID    296
#define VTILES   (2*(MROWS/128))  // 680
#define QTILES   (3*(MROWS/128))  // 1020

// level geometry
__device__ __constant__ int c_lvlWH[4]   = {128, 64, 32, 16};
__device__ __constant__ int c_lvlBase[4] = {0, 16384, 20480, 21504};

// ---------------- scratch ----------------
__device__ __align__(16) __half g_value_h[(size_t)BATCH*NHEADS*LEN_IN*HDIM];
__device__ float g_qproj[(size_t)MROWS*NQP];
__device__ __align__(16) __half g_samp_h[(size_t)MROWS*DMODEL];
__device__ __align__(16) __half g_q_h[(size_t)MROWS*KDIM];
__device__ __align__(16) __half g_x_h[(size_t)MROWS*KDIM];
__device__ __half g_Wq_hi[KDIM*NQP];
__device__ __half g_Wv_hi[KDIM*DMODEL];
__device__ __half g_Wo_hi[KDIM*DMODEL], g_Wo_lo[KDIM*DMODEL];
__device__ float g_bq[NQP];

// ---------------- PTX helpers ----------------
__device__ __forceinline__ uint32_t smem_u32(const void* p) {
    uint32_t a;
    asm("{ .reg .u64 t; cvta.to.shared.u64 t, %1; cvt.u32.u64 %0, t; }" : "=r"(a) : "l"(p));
    return a;
}
__device__ __forceinline__ void ldsm4(uint32_t* r, uint32_t a) {
    asm volatile("ldmatrix.sync.aligned.m8n8.x4.shared.b16 {%0,%1,%2,%3}, [%4];"
                 : "=r"(r[0]), "=r"(r[1]), "=r"(r[2]), "=r"(r[3]) : "r"(a));
}
__device__ __forceinline__ void ldsm4t(uint32_t* r, uint32_t a) {
    asm volatile("ldmatrix.sync.aligned.m8n8.x4.trans.shared.b16 {%0,%1,%2,%3}, [%4];"
                 : "=r"(r[0]), "=r"(r[1]), "=r"(r[2]), "=r"(r[3]) : "r"(a));
}
__device__ __forceinline__ void mma16816(float* c, const uint32_t* a, const uint32_t* b) {
    asm volatile("mma.sync.aligned.m16n8k16.row.col.f32.f16.f16.f32 "
                 "{%0,%1,%2,%3}, {%4,%5,%6,%7}, {%8,%9}, {%0,%1,%2,%3};"
                 : "+f"(c[0]), "+f"(c[1]), "+f"(c[2]), "+f"(c[3])
                 : "r"(a[0]), "r"(a[1]), "r"(a[2]), "r"(a[3]), "r"(b[0]), "r"(b[1]));
}
__device__ __forceinline__ void cpa16(uint32_t s, const void* g) {
    asm volatile("cp.async.cg.shared.global [%0], [%1], 16;" :: "r"(s), "l"(g));
}
#define CP_COMMIT()  asm volatile("cp.async.commit_group;" ::: "memory")
#define CP_WAIT(n)   asm volatile("cp.async.wait_group %0;" :: "n"(n) : "memory")

// packed f32x2 FMA: acc.{lo,hi} += w2.{lo,hi} * cvt(h2bits.{lo,hi})
// identical .rn rounding per lane as two scalar FFMAs -> bit-exact.
__device__ __forceinline__ void fma2h(unsigned long long& acc,
                                      unsigned long long w2, uint32_t h2bits) {
    asm("{\n\t"
        ".reg .b16 l, h;\n\t"
        ".reg .f32 lo, hi;\n\t"
        ".reg .b64 v2;\n\t"
        "mov.b32 {l, h}, %2;\n\t"
        "cvt.f32.f16 lo, l;\n\t"
        "cvt.f32.f16 hi, h;\n\t"
        "mov.b64 v2, {lo, hi};\n\t"
        "fma.rn.f32x2 %0, %1, v2, %0;\n\t"
        "}"
        : "+l"(acc) : "l"(w2), "r"(h2bits));
}

#define ASTRIDE 144
#define BSTRIDE 272
#define ABYTES  18432
#define BBYTES  17408
#define SSIZE1  (ABYTES+BBYTES)           // 35840
#define SM12    (2*SSIZE1)                // 71680
#define SSIZE2  (ABYTES+2*BBYTES)         // 53248
#define SMOUT   (2*SSIZE2)                // 106496

// ---------------- fused prep: weights + activations ----------------
__global__ void prep_all(const float* __restrict__ W_off, const float* __restrict__ b_off,
                         const float* __restrict__ W_attn, const float* __restrict__ b_attn,
                         const float* __restrict__ W_val, const float* __restrict__ W_out,
                         const float* __restrict__ q, const float* __restrict__ x)
{
    const int i = blockIdx.x * 256 + threadIdx.x;
    {
        const size_t e = (size_t)i * 4;
        const float4 v = *(const float4*)(q + e);
        __half2 a0 = __floats2half2_rn(v.x, v.y);
        __half2 a1 = __floats2half2_rn(v.z, v.w);
        *(uint2*)(g_q_h + e) = make_uint2(*(uint32_t*)&a0, *(uint32_t*)&a1);
        const float4 u = *(const float4*)(x + e);
        __half2 b0 = __floats2half2_rn(u.x, u.y);
        __half2 b1 = __floats2half2_rn(u.z, u.w);
        *(uint2*)(g_x_h + e) = make_uint2(*(uint32_t*)&b0, *(uint32_t*)&b1);
    }
    const int NQ = KDIM * NQP;
    const int NV = KDIM * DMODEL;
    if (i < NQ) {
        int k = i / NQP, n = i % NQP;
        float w = (n < 256) ? W_off[k * 256 + n] : W_attn[k * 128 + (n - 256)];
        g_Wq_hi[i] = __float2half_rn(w);
    } else if (i < NQ + NV) {
        int idx = i - NQ;
        g_Wv_hi[idx] = __float2half_rn(W_val[idx]);
    } else if (i < NQ + 2 * NV) {
        int idx = i - NQ - NV;
        float w = W_out[idx];
        __half hi = __float2half_rn(w);
        g_Wo_hi[idx] = hi;
        g_Wo_lo[idx] = __float2half_rn(w - __half2float(hi));
    }
    if (i < NQP) g_bq[i] = (i < 256) ? b_off[i] : b_attn[i - 256];
}

// ---------------- merged v+q GEMM: continuous cross-tile 2-stage pipeline ----
__global__ __launch_bounds__(256, 2)
void gemm_fused12(const float* __restrict__ b_val)
{
    extern __shared__ __align__(16) char dsm[];
    const uint32_t sb = smem_u32(dsm);

    const int tid  = threadIdx.x;
    const int wid  = tid >> 5;
    const int lane = tid & 31;
    const int m0   = (wid & 3) * 32;
    const int n0w  = (wid >> 2) * 64;

    const uint32_t aOff = (uint32_t)((m0 + (lane & 15)) * ASTRIDE + (lane >> 4) * 16);
    const uint32_t bOff = (uint32_t)(((lane & 7) + ((lane >> 3) & 1) * 8) * BSTRIDE
                                     + (lane >> 4) * 16 + n0w * 2);

    const int total = VTILES + QTILES;   // 1700
    const int bid   = blockIdx.x;
    const int ntcta = (total - bid + (int)gridDim.x - 1) / (int)gridDim.x;
    const int nslot = ntcta * 4;

    auto tileParams = [&](int ti, const __half*& Ah, const __half*& Wh,
                          int& N, int& bm, int& bn, bool& isV) {
        const int t = bid + ti * (int)gridDim.x;
        isV = (t < VTILES);
        const int tt = isV ? t : t - VTILES;
        const int nx = isV ? 2 : 3;
        N  = isV ? 256 : NQP;
        Ah = isV ? g_x_h : g_q_h;
        Wh = isV ? g_Wv_hi : g_Wq_hi;
        bm = (tt / nx) * 128;
        bn = (tt % nx) * 128;
    };

    auto issue = [&](int slot) {
        const __half *Ah, *Wh; int N, bm, bn; bool isV;
        tileParams(slot >> 2, Ah, Wh, N, bm, bn, isV);
        const int c = slot & 3;
        const uint32_t st = sb + (slot & 1) * SSIZE1;
        #pragma unroll
        for (int it = 0; it < 4; it++) {
            int idx = tid + it * 256;
            int r   = idx >> 3;
            int col = (idx & 7) * 8;
            cpa16(st + r * ASTRIDE + col * 2,
                  Ah + (size_t)(bm + r) * KDIM + c * 64 + col);
        }
        #pragma unroll
        for (int it = 0; it < 4; it++) {
            int idx = tid + it * 256;
            int r   = idx >> 4;
            int col = (idx & 15) * 8;
            cpa16(st + ABYTES + r * BSTRIDE + col * 2,
                  Wh + (size_t)(c * 64 + r) * N + bn + col);
        }
    };

    float acc[2][8][4];

    issue(0); CP_COMMIT();
    for (int s = 0; s < nslot; s++) {
        if ((s & 3) == 0) {
            #pragma unroll
            for (int i = 0; i < 2; i++)
                #pragma unroll
                for (int j = 0; j < 8; j++)
                    #pragma unroll
                    for (int q = 0; q < 4; q++) acc[i][j][q] = 0.f;
        }
        if (s + 1 < nslot) {
            issue(s + 1);
            CP_COMMIT();
            CP_WAIT(1);
        } else {
            CP_WAIT(0);
        }
        __syncthreads();

        const uint32_t st = sb + (s & 1) * SSIZE1;
        #pragma unroll
        for (int ks = 0; ks < 4; ks++) {
            uint32_t ah[2][4];
            ldsm4(ah[0], st + aOff + ks * 32);
            ldsm4(ah[1], st + aOff + 16 * ASTRIDE + ks * 32);
            #pragma unroll
            for (int hh = 0; hh < 2; hh++) {
                const uint32_t bks = bOff + ks * (16 * BSTRIDE) + hh * 64;
                uint32_t bh[8];
                ldsm4t(bh,     st + ABYTES + bks);
                ldsm4t(bh + 4, st + ABYTES + bks + 32);
                #pragma unroll
                for (int j = 0; j < 4; j++)
                    #pragma unroll
                    for (int i = 0; i < 2; i++)
                        mma16816(acc[i][hh * 4 + j], ah[i], bh + j * 2);
            }
        }
        __syncthreads();

        if ((s & 3) == 3) {
            const __half *Ah, *Wh; int N, bm, bn; bool isV;
            tileParams(s >> 2, Ah, Wh, N, bm, bn, isV);
            if (isV) {
                const int bb = (bm >= LEN_IN) ? 1 : 0;
                const int pixbase = bm - bb * LEN_IN;
                #pragma unroll
                for (int i = 0; i < 2; i++) {
                    const int pix = pixbase + m0 + i * 16 + (lane >> 2);
                    #pragma unroll
                    for (int j = 0; j < 8; j++) {
                        const int cc = bn + n0w + j * 8 + (lane & 3) * 2;
                        const int head = cc >> 5, chp = cc & 31;
                        const float2 bv = *(const float2*)(b_val + cc);
                        __half* dst = g_value_h
                            + ((size_t)(bb * NHEADS + head) * LEN_IN + pix) * HDIM + chp;
                        __half2 v0 = __floats2half2_rn(acc[i][j][0] + bv.x, acc[i][j][1] + bv.y);
                        __half2 v1 = __floats2half2_rn(acc[i][j][2] + bv.x, acc[i][j][3] + bv.y);
                        *(__half2*)dst = v0;
                        *(__half2*)(dst + 8 * HDIM) = v1;
                    }
                }
            } else {
                #pragma unroll
                for (int i = 0; i < 2; i++) {
                    const int r0 = bm + m0 + i * 16 + (lane >> 2);
                    #pragma unroll
                    for (int j = 0; j < 8; j++) {
                        const int cc = bn + n0w + j * 8 + (lane & 3) * 2;
                        const float2 bv = *(const float2*)(g_bq + cc);
                        float2 v0 = make_float2(acc[i][j][0] + bv.x, acc[i][j][1] + bv.y);
                        float2 v1 = make_float2(acc[i][j][2] + bv.x, acc[i][j][3] + bv.y);
                        *(float2*)(g_qproj + (size_t)r0 * NQP + cc) = v0;
                        *(float2*)(g_qproj + (size_t)(r0 + 8) * NQP + cc) = v1;
                    }
                }
            }
        }
    }
}

// ---------------- out-projection: 2-pass, 2-stage, persistent ----------------
__global__ __launch_bounds__(256, 2)
void gemm_out(const __half* __restrict__ Ah,
              const __half* __restrict__ Wh, const __half* __restrict__ Wl,
              const float* __restrict__ bias, float* __restrict__ C,
              int ntiles)
{
    extern __shared__ __align__(16) char dsm[];
    const uint32_t sb = smem_u32(dsm);

    const int tid  = threadIdx.x;
    const int wid  = tid >> 5;
    const int lane = tid & 31;
    const int m0   = (wid & 3) * 32;
    const int n0w  = (wid >> 2) * 64;
    const int N    = 256;

    const uint32_t aOff = (uint32_t)((m0 + (lane & 15)) * ASTRIDE + (lane >> 4) * 16);
    const uint32_t bOff = (uint32_t)(((lane & 7) + ((lane >> 3) & 1) * 8) * BSTRIDE
                                     + (lane >> 4) * 16 + n0w * 2);

    for (int t = blockIdx.x; t < ntiles; t += gridDim.x) {
        const int bm = (t >> 1) * 128;
        const int bn = (t & 1) * 128;

        float acc[2][8][4];
        #pragma unroll
        for (int i = 0; i < 2; i++)
            #pragma unroll
            for (int j = 0; j < 8; j++)
                #pragma unroll
                for (int q = 0; q < 4; q++) acc[i][j][q] = 0.f;

        auto issue = [&](int c, int buf) {
            const uint32_t st = sb + buf * SSIZE2;
            #pragma unroll
            for (int it = 0; it < 4; it++) {
                int idx = tid + it * 256;
                int r   = idx >> 3;
                int col = (idx & 7) * 8;
                cpa16(st + r * ASTRIDE + col * 2,
                      Ah + (size_t)(bm + r) * KDIM + c * 64 + col);
            }
            #pragma unroll
            for (int it = 0; it < 8; it++) {
                int idx = tid + it * 256;
                const __half* src = (it < 4) ? Wh : Wl;
                const uint32_t mo = (it < 4) ? 0u : (uint32_t)BBYTES;
                int j   = idx & 1023;
                int r   = j >> 4;
                int col = (j & 15) * 8;
                cpa16(st + ABYTES + mo + r * BSTRIDE + col * 2,
                      src + (size_t)(c * 64 + r) * N + bn + col);
            }
        };

        issue(0, 0);
        CP_COMMIT();
        for (int c = 0; c < 4; c++) {
            if (c < 3) {
                issue(c + 1, (c + 1) & 1);
                CP_COMMIT();
                CP_WAIT(1);
            } else {
                CP_WAIT(0);
            }
            __syncthreads();
            const uint32_t st = sb + (c & 1) * SSIZE2;
            #pragma unroll
            for (int ks = 0; ks < 4; ks++) {
                uint32_t ah[2][4];
                ldsm4(ah[0], st + aOff + ks * 32);
                ldsm4(ah[1], st + aOff + 16 * ASTRIDE + ks * 32);
                #pragma unroll
                for (int hh = 0; hh < 2; hh++) {
                    const uint32_t bks = bOff + ks * (16 * BSTRIDE) + hh * 64;
                    uint32_t bh[8], bl[8];
                    ldsm4t(bh,     st + ABYTES + bks);
                    ldsm4t(bh + 4, st + ABYTES + bks + 32);
                    ldsm4t(bl,     st + ABYTES + BBYTES + bks);
                    ldsm4t(bl + 4, st + ABYTES + BBYTES + bks + 32);
                    #pragma unroll
                    for (int j = 0; j < 4; j++)
                        #pragma unroll
                        for (int i = 0; i < 2; i++)
                            mma16816(acc[i][hh * 4 + j], ah[i], bh + j * 2);
                    #pragma unroll
                    for (int j = 0; j < 4; j++)
                        #pragma unroll
                        for (int i = 0; i < 2; i++)
                            mma16816(acc[i][hh * 4 + j], ah[i], bl + j * 2);
                }
            }
            __syncthreads();
        }

        #pragma unroll
        for (int i = 0; i < 2; i++) {
            const int r0 = bm + m0 + i * 16 + (lane >> 2);
            #pragma unroll
            for (int j = 0; j < 8; j++) {
                const int cc = bn + n0w + j * 8 + (lane & 3) * 2;
                const float2 bv = *(const float2*)(bias + cc);
                float2 v0 = make_float2(acc[i][j][0] + bv.x, acc[i][j][1] + bv.y);
                float2 v1 = make_float2(acc[i][j][2] + bv.x, acc[i][j][3] + bv.y);
                *(float2*)(C + (size_t)r0 * N + cc) = v0;
                *(float2*)(C + (size_t)(r0 + 8) * N + cc) = v1;
            }
        }
    }
}

// ---------------- block-staged softmax + deformable sampling ----------------
__global__ __launch_bounds__(256)
void deform_sample(const float* __restrict__ refp)
{
    __shared__ uint4 s_pw[GPB][32];

    const int tid = threadIdx.x;

    // ---------- phase 1 ----------
    {
        const int pi  = tid >> 3;
        const int sub = tid & 7;
        const int gp  = blockIdx.x * GPB + pi;
        const int h   = gp & 7;
        const int bq  = gp >> 3;
        const float* row = g_qproj + (size_t)bq * NQP;

        float lg0 = row[256 + h * 16 + 2 * sub];
        float lg1 = row[256 + h * 16 + 2 * sub + 1];
        float mx = fmaxf(lg0, lg1);
        #pragma unroll
        for (int s = 1; s < 8; s <<= 1) mx = fmaxf(mx, __shfl_xor_sync(0xffffffffu, mx, s));
        float e0 = __expf(lg0 - mx), e1 = __expf(lg1 - mx);
        float sm = e0 + e1;
        #pragma unroll
        for (int s = 1; s < 8; s <<= 1) sm += __shfl_xor_sync(0xffffffffu, sm, s);
        const float inv = __frcp_rn(sm);

        const float4 of = *(const float4*)(row + h * 32 + sub * 4);
        const int l = sub >> 1;
        const float2 rf = *(const float2*)(refp + (size_t)bq * 8 + l * 2);

        const int   WH   = c_lvlWH[l];
        const int   base = c_lvlBase[l];
        const float Wf   = (float)WH;

        #pragma unroll
        for (int pp = 0; pp < 2; pp++) {
            const float ox = pp ? of.z : of.x;
            const float oy = pp ? of.w : of.y;
            const float wat = (pp ? e1 : e0) * inv;

            const float ix = fmaf(rf.x, Wf, ox) - 0.5f;
            const float iy = fmaf(rf.y, Wf, oy) - 0.5f;
            const float x0f = floorf(ix), y0f = floorf(iy);
            const int   x0 = (int)x0f,    y0 = (int)y0f;
            const float fx = ix - x0f,    fy = iy - y0f;

            const int x1 = x0 + 1, y1 = y0 + 1;
            const float vx0 = (x0 >= 0 && x0 < WH) ? 1.f : 0.f;
            const float vx1 = (x1 >= 0 && x1 < WH) ? 1.f : 0.f;
            const float vy0 = (y0 >= 0 && y0 < WH) ? 1.f : 0.f;
            const float vy1 = (y1 >= 0 && y1 < WH) ? 1.f : 0.f;

            const int cx0 = min(max(x0, 0), WH - 1);
            const int cx1 = min(max(x1, 0), WH - 1);
            const int cy0 = min(max(y0, 0), WH - 1);
            const int cy1 = min(max(y1, 0), WH - 1);

            const int p = sub * 2 + pp;
            s_pw[pi][p * 2 + 0] = make_uint4(
                (uint32_t)(base + cy0 * WH + cx0) << 6,
                __float_as_uint((1.f - fx) * (1.f - fy) * vy0 * vx0 * wat),
                (uint32_t)(base + cy0 * WH + cx1) << 6,
                __float_as_uint(fx * (1.f - fy) * vy0 * vx1 * wat));
            s_pw[pi][p * 2 + 1] = make_uint4(
                (uint32_t)(base + cy1 * WH + cx0) << 6,
                __float_as_uint((1.f - fx) * fy * vy1 * vx0 * wat),
                (uint32_t)(base + cy1 * WH + cx1) << 6,
                __float_as_uint(fx * fy * vy1 * vx1 * wat));
        }
    }
    __syncthreads();

    // ---------- phase 2 (packed f32x2 FMA; bit-identical to scalar) ----------
    const int wid  = tid >> 5;
    const int lane = tid & 31;
    const int g    = lane >> 2;
    const int quad = lane & 3;

    #pragma unroll 1
    for (int pp = 0; pp < 4; pp++) {
        const int pi = wid * 4 + pp;
        const int gp = blockIdx.x * GPB + pi;
        const int h  = gp & 7;
        const int bq = gp >> 3;
        const int b  = (bq >= LQ) ? 1 : 0;
        const char* vbc = (const char*)g_value_h
            + ((size_t)(b * NHEADS + h) * LEN_IN) * (HDIM * 2) + quad * 16;
        const char* pwb = (const char*)&s_pw[pi][0] + g * 8;

        unsigned long long a01 = 0ull, a23 = 0ull, a45 = 0ull, a67 = 0ull;
        #pragma unroll
        for (int t = 0; t < 8; t++) {
            const uint2 pw = *(const uint2*)(pwb + t * 64);
            unsigned long long w2;
            asm("mov.b64 %0, {%1, %1};" : "=l"(w2) : "r"(pw.y));
            const uint4 v = *(const uint4*)(vbc + pw.x);
            fma2h(a01, w2, v.x);
            fma2h(a23, w2, v.y);
            fma2h(a45, w2, v.z);
            fma2h(a67, w2, v.w);
        }
        float2 A01 = *(float2*)&a01;
        float2 A23 = *(float2*)&a23;
        float2 A45 = *(float2*)&a45;
        float2 A67 = *(float2*)&a67;
        float a0 = A01.x, a1 = A01.y, a2 = A23.x, a3 = A23.y;
        float a4 = A45.x, a5 = A45.y, a6 = A67.x, a7 = A67.y;
        #pragma unroll
        for (int s = 4; s <= 16; s <<= 1) {
            a0 += __shfl_xor_sync(0xffffffffu, a0, s);
            a1 += __shfl_xor_sync(0xffffffffu, a1, s);
            a2 += __shfl_xor_sync(0xffffffffu, a2, s);
            a3 += __shfl_xor_sync(0xffffffffu, a3, s);
            a4 += __shfl_xor_sync(0xffffffffu, a4, s);
            a5 += __shfl_xor_sync(0xffffffffu, a5, s);
            a6 += __shfl_xor_sync(0xffffffffu, a6, s);
            a7 += __shfl_xor_sync(0xffffffffu, a7, s);
        }
        if (lane < 4) {
            __half2 h0 = __floats2half2_rn(a0, a1);
            __half2 h1 = __floats2half2_rn(a2, a3);
            __half2 h2 = __floats2half2_rn(a4, a5);
            __half2 h3 = __floats2half2_rn(a6, a7);
            uint4 st = make_uint4(*(uint32_t*)&h0, *(uint32_t*)&h1,
                                  *(uint32_t*)&h2, *(uint32_t*)&h3);
            *(uint4*)((char*)g_samp_h + (size_t)bq * (DMODEL * 2) + h * 64 + lane * 16) = st;
        }
    }
}

// ---------------- launch ----------------
extern "C" void kernel_launch(void* const* d_in, const int* in_sizes, int n_in,
                              void* d_out, int out_size)
{
    (void)in_sizes; (void)n_in; (void)out_size;
    const float* query  = (const float*)d_in[0];
    const float* refp   = (const float*)d_in[1];
    const float* xin    = (const float*)d_in[2];
    const float* W_off  = (const float*)d_in[3];
    const float* b_off  = (const float*)d_in[4];
    const float* W_attn = (const float*)d_in[5];
    const float* b_attn = (const float*)d_in[6];
    const float* W_val  = (const float*)d_in[7];
    const float* b_val  = (const float*)d_in[8];
    const float* W_out  = (const float*)d_in[9];
    const float* b_out  = (const float*)d_in[10];
    float* out = (float*)d_out;

    __half *p_samp_h, *p_Wo_hi, *p_Wo_lo;
    cudaGetSymbolAddress((void**)&p_samp_h, g_samp_h);
    cudaGetSymbolAddress((void**)&p_Wo_hi,  g_Wo_hi);
    cudaGetSymbolAddress((void**)&p_Wo_lo,  g_Wo_lo);

    cudaFuncSetAttribute(gemm_fused12, cudaFuncAttributeMaxDynamicSharedMemorySize, SM12);
    cudaFuncSetAttribute(gemm_out,     cudaFuncAttributeMaxDynamicSharedMemorySize, SMOUT);

    // 0) fused prep (weights + fp16 activations)
    prep_all<<<(MROWS * KDIM / 4) / 256, 256>>>(
        W_off, b_off, W_attn, b_attn, W_val, W_out, query, xin);

    // 1+2) merged value + qproj GEMM (1-pass, continuous cross-tile pipeline)
    gemm_fused12<<<PGRID, 256, SM12>>>(b_val);

    // 3) block-staged softmax + deformable sampling -> fp16 samp
    deform_sample<<<(MROWS * NHEADS) / GPB, 256>>>(refp);

    // 4) output projection: fp16 A (exact), 2-pass
    gemm_out<<<PGRID, 256, SMOUT>>>(p_samp_h, p_Wo_hi, p_Wo_lo, b_out, out, VTILES);
}

// round 17
// speedup vs baseline: 1.0767x; 1.0767x over previous
#include <cuda_runtime.h>
#include <cuda_fp16.h>
#include <math.h>
#include <stdint.h>

// ---------------- problem constants ----------------
#define BATCH    2
#define LQ       21760
#define LEN_IN   21760
#define DMODEL   256
#define NHEADS   8
#define HDIM     32
#define MROWS    (BATCH*LQ)       // 43520
#define NQP      384
#define KDIM     256
#define GPB      32
#define PGRID    296
#define VTILES   (2*(MROWS/128))  // 680
#define QTILES   (3*(MROWS/128))  // 1020

// level geometry
__device__ __constant__ int c_lvlWH[4]   = {128, 64, 32, 16};
__device__ __constant__ int c_lvlBase[4] = {0, 16384, 20480, 21504};

// ---------------- scratch ----------------
__device__ __align__(16) __half g_value_h[(size_t)BATCH*NHEADS*LEN_IN*HDIM];
__device__ float g_qproj[(size_t)MROWS*NQP];
__device__ __align__(16) __half g_samp_h[(size_t)MROWS*DMODEL];
__device__ __align__(16) __half g_q_h[(size_t)MROWS*KDIM];
__device__ __align__(16) __half g_x_h[(size_t)MROWS*KDIM];
__device__ __half g_Wq_hi[KDIM*NQP];
__device__ __half g_Wv_hi[KDIM*DMODEL];
__device__ __half g_Wo_hi[KDIM*DMODEL];
__device__ float g_bq[NQP];

// ---------------- PTX helpers ----------------
__device__ __forceinline__ uint32_t smem_u32(const void* p) {
    uint32_t a;
    asm("{ .reg .u64 t; cvta.to.shared.u64 t, %1; cvt.u32.u64 %0, t; }" : "=r"(a) : "l"(p));
    return a;
}
__device__ __forceinline__ void ldsm4(uint32_t* r, uint32_t a) {
    asm volatile("ldmatrix.sync.aligned.m8n8.x4.shared.b16 {%0,%1,%2,%3}, [%4];"
                 : "=r"(r[0]), "=r"(r[1]), "=r"(r[2]), "=r"(r[3]) : "r"(a));
}
__device__ __forceinline__ void ldsm4t(uint32_t* r, uint32_t a) {
    asm volatile("ldmatrix.sync.aligned.m8n8.x4.trans.shared.b16 {%0,%1,%2,%3}, [%4];"
                 : "=r"(r[0]), "=r"(r[1]), "=r"(r[2]), "=r"(r[3]) : "r"(a));
}
__device__ __forceinline__ void mma16816(float* c, const uint32_t* a, const uint32_t* b) {
    asm volatile("mma.sync.aligned.m16n8k16.row.col.f32.f16.f16.f32 "
                 "{%0,%1,%2,%3}, {%4,%5,%6,%7}, {%8,%9}, {%0,%1,%2,%3};"
                 : "+f"(c[0]), "+f"(c[1]), "+f"(c[2]), "+f"(c[3])
                 : "r"(a[0]), "r"(a[1]), "r"(a[2]), "r"(a[3]), "r"(b[0]), "r"(b[1]));
}
__device__ __forceinline__ void cpa16(uint32_t s, const void* g) {
    asm volatile("cp.async.cg.shared.global [%0], [%1], 16;" :: "r"(s), "l"(g));
}
#define CP_COMMIT()  asm volatile("cp.async.commit_group;" ::: "memory")
#define CP_WAIT(n)   asm volatile("cp.async.wait_group %0;" :: "n"(n) : "memory")

#define ASTRIDE 144
#define BSTRIDE 272
#define ABYTES  18432
#define BBYTES  17408
#define SSIZE1  (ABYTES+BBYTES)           // 35840
#define SM12    (2*SSIZE1)                // 71680

// ---------------- fused prep: weights + activations ----------------
__global__ void prep_all(const float* __restrict__ W_off, const float* __restrict__ b_off,
                         const float* __restrict__ W_attn, const float* __restrict__ b_attn,
                         const float* __restrict__ W_val, const float* __restrict__ W_out,
                         const float* __restrict__ q, const float* __restrict__ x)
{
    const int i = blockIdx.x * 256 + threadIdx.x;
    {
        const size_t e = (size_t)i * 4;
        const float4 v = *(const float4*)(q + e);
        __half2 a0 = __floats2half2_rn(v.x, v.y);
        __half2 a1 = __floats2half2_rn(v.z, v.w);
        *(uint2*)(g_q_h + e) = make_uint2(*(uint32_t*)&a0, *(uint32_t*)&a1);
        const float4 u = *(const float4*)(x + e);
        __half2 b0 = __floats2half2_rn(u.x, u.y);
        __half2 b1 = __floats2half2_rn(u.z, u.w);
        *(uint2*)(g_x_h + e) = make_uint2(*(uint32_t*)&b0, *(uint32_t*)&b1);
    }
    const int NQ = KDIM * NQP;
    const int NV = KDIM * DMODEL;
    if (i < NQ) {
        int k = i / NQP, n = i % NQP;
        float w = (n < 256) ? W_off[k * 256 + n] : W_attn[k * 128 + (n - 256)];
        g_Wq_hi[i] = __float2half_rn(w);
    } else if (i < NQ + NV) {
        int idx = i - NQ;
        g_Wv_hi[idx] = __float2half_rn(W_val[idx]);
    } else if (i < NQ + 2 * NV) {
        int idx = i - NQ - NV;
        g_Wo_hi[idx] = __float2half_rn(W_out[idx]);
    }
    if (i < NQP) g_bq[i] = (i < 256) ? b_off[i] : b_attn[i - 256];
}

// ---------------- merged v+q GEMM: continuous cross-tile 2-stage pipeline ----
__global__ __launch_bounds__(256, 2)
void gemm_fused12(const float* __restrict__ b_val)
{
    extern __shared__ __align__(16) char dsm[];
    const uint32_t sb = smem_u32(dsm);

    const int tid  = threadIdx.x;
    const int wid  = tid >> 5;
    const int lane = tid & 31;
    const int m0   = (wid & 3) * 32;
    const int n0w  = (wid >> 2) * 64;

    const uint32_t aOff = (uint32_t)((m0 + (lane & 15)) * ASTRIDE + (lane >> 4) * 16);
    const uint32_t bOff = (uint32_t)(((lane & 7) + ((lane >> 3) & 1) * 8) * BSTRIDE
                                     + (lane >> 4) * 16 + n0w * 2);

    const int total = VTILES + QTILES;   // 1700
    const int bid   = blockIdx.x;
    const int ntcta = (total - bid + (int)gridDim.x - 1) / (int)gridDim.x;
    const int nslot = ntcta * 4;

    auto tileParams = [&](int ti, const __half*& Ah, const __half*& Wh,
                          int& N, int& bm, int& bn, bool& isV) {
        const int t = bid + ti * (int)gridDim.x;
        isV = (t < VTILES);
        const int tt = isV ? t : t - VTILES;
        const int nx = isV ? 2 : 3;
        N  = isV ? 256 : NQP;
        Ah = isV ? g_x_h : g_q_h;
        Wh = isV ? g_Wv_hi : g_Wq_hi;
        bm = (tt / nx) * 128;
        bn = (tt % nx) * 128;
    };

    auto issue = [&](int slot) {
        const __half *Ah, *Wh; int N, bm, bn; bool isV;
        tileParams(slot >> 2, Ah, Wh, N, bm, bn, isV);
        const int c = slot & 3;
        const uint32_t st = sb + (slot & 1) * SSIZE1;
        #pragma unroll
        for (int it = 0; it < 4; it++) {
            int idx = tid + it * 256;
            int r   = idx >> 3;
            int col = (idx & 7) * 8;
            cpa16(st + r * ASTRIDE + col * 2,
                  Ah + (size_t)(bm + r) * KDIM + c * 64 + col);
        }
        #pragma unroll
        for (int it = 0; it < 4; it++) {
            int idx = tid + it * 256;
            int r   = idx >> 4;
            int col = (idx & 15) * 8;
            cpa16(st + ABYTES + r * BSTRIDE + col * 2,
                  Wh + (size_t)(c * 64 + r) * N + bn + col);
        }
    };

    float acc[2][8][4];

    issue(0); CP_COMMIT();
    for (int s = 0; s < nslot; s++) {
        if ((s & 3) == 0) {
            #pragma unroll
            for (int i = 0; i < 2; i++)
                #pragma unroll
                for (int j = 0; j < 8; j++)
                    #pragma unroll
                    for (int q = 0; q < 4; q++) acc[i][j][q] = 0.f;
        }
        if (s + 1 < nslot) {
            issue(s + 1);
            CP_COMMIT();
            CP_WAIT(1);
        } else {
            CP_WAIT(0);
        }
        __syncthreads();

        const uint32_t st = sb + (s & 1) * SSIZE1;
        #pragma unroll
        for (int ks = 0; ks < 4; ks++) {
            uint32_t ah[2][4];
            ldsm4(ah[0], st + aOff + ks * 32);
            ldsm4(ah[1], st + aOff + 16 * ASTRIDE + ks * 32);
            #pragma unroll
            for (int hh = 0; hh < 2; hh++) {
                const uint32_t bks = bOff + ks * (16 * BSTRIDE) + hh * 64;
                uint32_t bh[8];
                ldsm4t(bh,     st + ABYTES + bks);
                ldsm4t(bh + 4, st + ABYTES + bks + 32);
                #pragma unroll
                for (int j = 0; j < 4; j++)
                    #pragma unroll
                    for (int i = 0; i < 2; i++)
                        mma16816(acc[i][hh * 4 + j], ah[i], bh + j * 2);
            }
        }
        __syncthreads();

        if ((s & 3) == 3) {
            const __half *Ah, *Wh; int N, bm, bn; bool isV;
            tileParams(s >> 2, Ah, Wh, N, bm, bn, isV);
            if (isV) {
                const int bb = (bm >= LEN_IN) ? 1 : 0;
                const int pixbase = bm - bb * LEN_IN;
                #pragma unroll
                for (int i = 0; i < 2; i++) {
                    const int pix = pixbase + m0 + i * 16 + (lane >> 2);
                    #pragma unroll
                    for (int j = 0; j < 8; j++) {
                        const int cc = bn + n0w + j * 8 + (lane & 3) * 2;
                        const int head = cc >> 5, chp = cc & 31;
                        const float2 bv = *(const float2*)(b_val + cc);
                        __half* dst = g_value_h
                            + ((size_t)(bb * NHEADS + head) * LEN_IN + pix) * HDIM + chp;
                        __half2 v0 = __floats2half2_rn(acc[i][j][0] + bv.x, acc[i][j][1] + bv.y);
                        __half2 v1 = __floats2half2_rn(acc[i][j][2] + bv.x, acc[i][j][3] + bv.y);
                        *(__half2*)dst = v0;
                        *(__half2*)(dst + 8 * HDIM) = v1;
                    }
                }
            } else {
                #pragma unroll
                for (int i = 0; i < 2; i++) {
                    const int r0 = bm + m0 + i * 16 + (lane >> 2);
                    #pragma unroll
                    for (int j = 0; j < 8; j++) {
                        const int cc = bn + n0w + j * 8 + (lane & 3) * 2;
                        const float2 bv = *(const float2*)(g_bq + cc);
                        float2 v0 = make_float2(acc[i][j][0] + bv.x, acc[i][j][1] + bv.y);
                        float2 v1 = make_float2(acc[i][j][2] + bv.x, acc[i][j][3] + bv.y);
                        *(float2*)(g_qproj + (size_t)r0 * NQP + cc) = v0;
                        *(float2*)(g_qproj + (size_t)(r0 + 8) * NQP + cc) = v1;
                    }
                }
            }
        }
    }
}

// ---------------- out-projection: 1-pass, 2-stage, persistent ----------------
__global__ __launch_bounds__(256, 2)
void gemm_out(const __half* __restrict__ Ah, const __half* __restrict__ Wh,
              const float* __restrict__ bias, float* __restrict__ C,
              int ntiles)
{
    extern __shared__ __align__(16) char dsm[];
    const uint32_t sb = smem_u32(dsm);

    const int tid  = threadIdx.x;
    const int wid  = tid >> 5;
    const int lane = tid & 31;
    const int m0   = (wid & 3) * 32;
    const int n0w  = (wid >> 2) * 64;
    const int N    = 256;

    const uint32_t aOff = (uint32_t)((m0 + (lane & 15)) * ASTRIDE + (lane >> 4) * 16);
    const uint32_t bOff = (uint32_t)(((lane & 7) + ((lane >> 3) & 1) * 8) * BSTRIDE
                                     + (lane >> 4) * 16 + n0w * 2);

    for (int t = blockIdx.x; t < ntiles; t += gridDim.x) {
        const int bm = (t >> 1) * 128;
        const int bn = (t & 1) * 128;

        float acc[2][8][4];
        #pragma unroll
        for (int i = 0; i < 2; i++)
            #pragma unroll
            for (int j = 0; j < 8; j++)
                #pragma unroll
                for (int q = 0; q < 4; q++) acc[i][j][q] = 0.f;

        auto issue = [&](int c, int buf) {
            const uint32_t st = sb + buf * SSIZE1;
            #pragma unroll
            for (int it = 0; it < 4; it++) {
                int idx = tid + it * 256;
                int r   = idx >> 3;
                int col = (idx & 7) * 8;
                cpa16(st + r * ASTRIDE + col * 2,
                      Ah + (size_t)(bm + r) * KDIM + c * 64 + col);
            }
            #pragma unroll
            for (int it = 0; it < 4; it++) {
                int idx = tid + it * 256;
                int r   = idx >> 4;
                int col = (idx & 15) * 8;
                cpa16(st + ABYTES + r * BSTRIDE + col * 2,
                      Wh + (size_t)(c * 64 + r) * N + bn + col);
            }
        };

        issue(0, 0);
        CP_COMMIT();
        for (int c = 0; c < 4; c++) {
            if (c < 3) {
                issue(c + 1, (c + 1) & 1);
                CP_COMMIT();
                CP_WAIT(1);
            } else {
                CP_WAIT(0);
            }
            __syncthreads();
            const uint32_t st = sb + (c & 1) * SSIZE1;
            #pragma unroll
            for (int ks = 0; ks < 4; ks++) {
                uint32_t ah[2][4];
                ldsm4(ah[0], st + aOff + ks * 32);
                ldsm4(ah[1], st + aOff + 16 * ASTRIDE + ks * 32);
                #pragma unroll
                for (int hh = 0; hh < 2; hh++) {
                    const uint32_t bks = bOff + ks * (16 * BSTRIDE) + hh * 64;
                    uint32_t bh[8];
                    ldsm4t(bh,     st + ABYTES + bks);
                    ldsm4t(bh + 4, st + ABYTES + bks + 32);
                    #pragma unroll
                    for (int j = 0; j < 4; j++)
                        #pragma unroll
                        for (int i = 0; i < 2; i++)
                            mma16816(acc[i][hh * 4 + j], ah[i], bh + j * 2);
                }
            }
            __syncthreads();
        }

        #pragma unroll
        for (int i = 0; i < 2; i++) {
            const int r0 = bm + m0 + i * 16 + (lane >> 2);
            #pragma unroll
            for (int j = 0; j < 8; j++) {
                const int cc = bn + n0w + j * 8 + (lane & 3) * 2;
                const float2 bv = *(const float2*)(bias + cc);
                float2 v0 = make_float2(acc[i][j][0] + bv.x, acc[i][j][1] + bv.y);
                float2 v1 = make_float2(acc[i][j][2] + bv.x, acc[i][j][3] + bv.y);
                *(float2*)(C + (size_t)r0 * N + cc) = v0;
                *(float2*)(C + (size_t)(r0 + 8) * N + cc) = v1;
            }
        }
    }
}

// ---------------- block-staged softmax + deformable sampling ----------------
__global__ __launch_bounds__(256)
void deform_sample(const float* __restrict__ refp)
{
    __shared__ uint4 s_pw[GPB][32];

    const int tid = threadIdx.x;

    // ---------- phase 1 ----------
    {
        const int pi  = tid >> 3;
        const int sub = tid & 7;
        const int gp  = blockIdx.x * GPB + pi;
        const int h   = gp & 7;
        const int bq  = gp >> 3;
        const float* row = g_qproj + (size_t)bq * NQP;

        float lg0 = row[256 + h * 16 + 2 * sub];
        float lg1 = row[256 + h * 16 + 2 * sub + 1];
        float mx = fmaxf(lg0, lg1);
        #pragma unroll
        for (int s = 1; s < 8; s <<= 1) mx = fmaxf(mx, __shfl_xor_sync(0xffffffffu, mx, s));
        float e0 = __expf(lg0 - mx), e1 = __expf(lg1 - mx);
        float sm = e0 + e1;
        #pragma unroll
        for (int s = 1; s < 8; s <<= 1) sm += __shfl_xor_sync(0xffffffffu, sm, s);
        const float inv = __frcp_rn(sm);

        const float4 of = *(const float4*)(row + h * 32 + sub * 4);
        const int l = sub >> 1;
        const float2 rf = *(const float2*)(refp + (size_t)bq * 8 + l * 2);

        const int   WH   = c_lvlWH[l];
        const int   base = c_lvlBase[l];
        const float Wf   = (float)WH;

        #pragma unroll
        for (int pp = 0; pp < 2; pp++) {
            const float ox = pp ? of.z : of.x;
            const float oy = pp ? of.w : of.y;
            const float wat = (pp ? e1 : e0) * inv;

            const float ix = fmaf(rf.x, Wf, ox) - 0.5f;
            const float iy = fmaf(rf.y, Wf, oy) - 0.5f;
            const float x0f = floorf(ix), y0f = floorf(iy);
            const int   x0 = (int)x0f,    y0 = (int)y0f;
            const float fx = ix - x0f,    fy = iy - y0f;

            const int x1 = x0 + 1, y1 = y0 + 1;
            const float vx0 = (x0 >= 0 && x0 < WH) ? 1.f : 0.f;
            const float vx1 = (x1 >= 0 && x1 < WH) ? 1.f : 0.f;
            const float vy0 = (y0 >= 0 && y0 < WH) ? 1.f : 0.f;
            const float vy1 = (y1 >= 0 && y1 < WH) ? 1.f : 0.f;

            const int cx0 = min(max(x0, 0), WH - 1);
            const int cx1 = min(max(x1, 0), WH - 1);
            const int cy0 = min(max(y0, 0), WH - 1);
            const int cy1 = min(max(y1, 0), WH - 1);

            const int p = sub * 2 + pp;
            s_pw[pi][p * 2 + 0] = make_uint4(
                (uint32_t)(base + cy0 * WH + cx0) << 6,
                __float_as_uint((1.f - fx) * (1.f - fy) * vy0 * vx0 * wat),
                (uint32_t)(base + cy0 * WH + cx1) << 6,
                __float_as_uint(fx * (1.f - fy) * vy0 * vx1 * wat));
            s_pw[pi][p * 2 + 1] = make_uint4(
                (uint32_t)(base + cy1 * WH + cx0) << 6,
                __float_as_uint((1.f - fx) * fy * vy1 * vx0 * wat),
                (uint32_t)(base + cy1 * WH + cx1) << 6,
                __float_as_uint(fx * fy * vy1 * vx1 * wat));
        }
    }
    __syncthreads();

    // ---------- phase 2 ----------
    const int wid  = tid >> 5;
    const int lane = tid & 31;
    const int g    = lane >> 2;
    const int quad = lane & 3;

    #pragma unroll 1
    for (int pp = 0; pp < 4; pp++) {
        const int pi = wid * 4 + pp;
        const int gp = blockIdx.x * GPB + pi;
        const int h  = gp & 7;
        const int bq = gp >> 3;
        const int b  = (bq >= LQ) ? 1 : 0;
        const char* vbc = (const char*)g_value_h
            + ((size_t)(b * NHEADS + h) * LEN_IN) * (HDIM * 2) + quad * 16;
        const char* pwb = (const char*)&s_pw[pi][0] + g * 8;

        float a0 = 0.f, a1 = 0.f, a2 = 0.f, a3 = 0.f, a4 = 0.f, a5 = 0.f, a6 = 0.f, a7 = 0.f;
        #pragma unroll
        for (int t = 0; t < 8; t++) {
            const uint2 pw = *(const uint2*)(pwb + t * 64);
            const float w  = __uint_as_float(pw.y);
            const uint4 v  = *(const uint4*)(vbc + pw.x);
            const float2 f0 = __half22float2(*(const __half2*)&v.x);
            const float2 f1 = __half22float2(*(const __half2*)&v.y);
            const float2 f2 = __half22float2(*(const __half2*)&v.z);
            const float2 f3 = __half22float2(*(const __half2*)&v.w);
            a0 = fmaf(w, f0.x, a0); a1 = fmaf(w, f0.y, a1);
            a2 = fmaf(w, f1.x, a2); a3 = fmaf(w, f1.y, a3);
            a4 = fmaf(w, f2.x, a4); a5 = fmaf(w, f2.y, a5);
            a6 = fmaf(w, f3.x, a6); a7 = fmaf(w, f3.y, a7);
        }
        #pragma unroll
        for (int s = 4; s <= 16; s <<= 1) {
            a0 += __shfl_xor_sync(0xffffffffu, a0, s);
            a1 += __shfl_xor_sync(0xffffffffu, a1, s);
            a2 += __shfl_xor_sync(0xffffffffu, a2, s);
            a3 += __shfl_xor_sync(0xffffffffu, a3, s);
            a4 += __shfl_xor_sync(0xffffffffu, a4, s);
            a5 += __shfl_xor_sync(0xffffffffu, a5, s);
            a6 += __shfl_xor_sync(0xffffffffu, a6, s);
            a7 += __shfl_xor_sync(0xffffffffu, a7, s);
        }
        if (lane < 4) {
            __half2 h0 = __floats2half2_rn(a0, a1);
            __half2 h1 = __floats2half2_rn(a2, a3);
            __half2 h2 = __floats2half2_rn(a4, a5);
            __half2 h3 = __floats2half2_rn(a6, a7);
            uint4 st = make_uint4(*(uint32_t*)&h0, *(uint32_t*)&h1,
                                  *(uint32_t*)&h2, *(uint32_t*)&h3);
            *(uint4*)((char*)g_samp_h + (size_t)bq * (DMODEL * 2) + h * 64 + lane * 16) = st;
        }
    }
}

// ---------------- launch ----------------
extern "C" void kernel_launch(void* const* d_in, const int* in_sizes, int n_in,
                              void* d_out, int out_size)
{
    (void)in_sizes; (void)n_in; (void)out_size;
    const float* query  = (const float*)d_in[0];
    const float* refp   = (const float*)d_in[1];
    const float* xin    = (const float*)d_in[2];
    const float* W_off  = (const float*)d_in[3];
    const float* b_off  = (const float*)d_in[4];
    const float* W_attn = (const float*)d_in[5];
    const float* b_attn = (const float*)d_in[6];
    const float* W_val  = (const float*)d_in[7];
    const float* b_val  = (const float*)d_in[8];
    const float* W_out  = (const float*)d_in[9];
    const float* b_out  = (const float*)d_in[10];
    float* out = (float*)d_out;

    __half *p_samp_h, *p_Wo_hi;
    cudaGetSymbolAddress((void**)&p_samp_h, g_samp_h);
    cudaGetSymbolAddress((void**)&p_Wo_hi,  g_Wo_hi);

    cudaFuncSetAttribute(gemm_fused12, cudaFuncAttributeMaxDynamicSharedMemorySize, SM12);
    cudaFuncSetAttribute(gemm_out,     cudaFuncAttributeMaxDynamicSharedMemorySize, SM12);

    // 0) fused prep (weights + fp16 activations)
    prep_all<<<(MROWS * KDIM / 4) / 256, 256>>>(
        W_off, b_off, W_attn, b_attn, W_val, W_out, query, xin);

    // 1+2) merged value + qproj GEMM (1-pass, continuous cross-tile pipeline)
    gemm_fused12<<<PGRID, 256, SM12>>>(b_val);

    // 3) block-staged softmax + deformable sampling -> fp16 samp
    deform_sample<<<(MROWS * NHEADS) / GPB, 256>>>(refp);

    // 4) output projection: fp16 A (exact), 1-pass
    gemm_out<<<PGRID, 256, SM12>>>(p_samp_h, p_Wo_hi, b_out, out, VTILES);
}